// round 1
// baseline (speedup 1.0000x reference)
#include <cuda_runtime.h>
#include <cstdint>

// ---------------- problem dims (fixed) ----------------
#define B_   4
#define L_   2048
#define DM   1024      // d_model
#define DI   2048      // d_inner
#define DS   32        // d_state
#define DR   64        // dt_rank
#define M_   (B_ * L_) // 8192 rows
#define LN_EPS 1e-5f

// ---------------- scratch (device globals; no allocs allowed) ----------------
__device__ float g_xz[(size_t)M_ * 2 * DI];   // 8192 x 4096 (xi | z)
__device__ float g_xc[(size_t)M_ * DI];       // conv+silu output (u)
__device__ float g_dbc[(size_t)M_ * 128];     // dt(64) | B(32) | C(32)
__device__ float g_delta[(size_t)M_ * DI];    // softplus(dt @ dt_proj + b)
__device__ float g_y[(size_t)M_ * DI];        // gated scan output

// ---------------- helpers ----------------
__device__ __forceinline__ float siluf(float x) { return x / (1.f + expf(-x)); }
__device__ __forceinline__ float softplusf(float x) {
    return (x > 20.f) ? x : log1pf(expf(x));
}

// ---------------- generic fp32 SGEMM ----------------
// C[M,N] = A[M,K](lda) * B[K,N](ldb)  (+bias, +softplus if ACT==1)
template<int BM, int BN, int BK, int TM, int TN, int ACT>
__global__ void sgemm_kernel(const float* __restrict__ A,
                             const float* __restrict__ Bm,
                             const float* __restrict__ bias,
                             float* __restrict__ C,
                             int M, int N, int K, int lda, int ldb, int ldc) {
    constexpr int THREADS = (BM / TM) * (BN / TN);
    __shared__ float As[BK][BM];
    __shared__ float Bs[BK][BN];

    const int tid = threadIdx.x;
    const int bm = blockIdx.y * BM;
    const int bn = blockIdx.x * BN;
    const int tx = tid % (BN / TN);
    const int ty = tid / (BN / TN);

    float acc[TM][TN];
#pragma unroll
    for (int i = 0; i < TM; i++)
#pragma unroll
        for (int j = 0; j < TN; j++) acc[i][j] = 0.f;

    constexpr int A_ITERS = (BM * BK) / (THREADS * 4);
    constexpr int B_ITERS = (BK * BN) / (THREADS * 4);

    for (int k0 = 0; k0 < K; k0 += BK) {
#pragma unroll
        for (int i = 0; i < A_ITERS; i++) {
            int idx = tid + i * THREADS;         // over BM * (BK/4)
            int ar = idx / (BK / 4);
            int ac = (idx % (BK / 4)) * 4;
            float4 v = *(const float4*)&A[(size_t)(bm + ar) * lda + k0 + ac];
            As[ac + 0][ar] = v.x;
            As[ac + 1][ar] = v.y;
            As[ac + 2][ar] = v.z;
            As[ac + 3][ar] = v.w;
        }
#pragma unroll
        for (int i = 0; i < B_ITERS; i++) {
            int idx = tid + i * THREADS;         // over BK * (BN/4)
            int br = idx / (BN / 4);
            int bc = (idx % (BN / 4)) * 4;
            *(float4*)&Bs[br][bc] =
                *(const float4*)&Bm[(size_t)(k0 + br) * ldb + bn + bc];
        }
        __syncthreads();

#pragma unroll
        for (int k = 0; k < BK; k++) {
            float ra[TM], rb[TN];
#pragma unroll
            for (int i = 0; i < TM; i++) ra[i] = As[k][ty * TM + i];
#pragma unroll
            for (int j = 0; j < TN; j++) rb[j] = Bs[k][tx * TN + j];
#pragma unroll
            for (int i = 0; i < TM; i++)
#pragma unroll
                for (int j = 0; j < TN; j++)
                    acc[i][j] = fmaf(ra[i], rb[j], acc[i][j]);
        }
        __syncthreads();
    }

#pragma unroll
    for (int i = 0; i < TM; i++) {
        int r = bm + ty * TM + i;
#pragma unroll
        for (int j = 0; j < TN; j += 4) {
            int c = bn + tx * TN + j;
            float4 v;
            v.x = acc[i][j + 0];
            v.y = acc[i][j + 1];
            v.z = acc[i][j + 2];
            v.w = acc[i][j + 3];
            if (ACT == 1) {
                v.x = softplusf(v.x + bias[c + 0]);
                v.y = softplusf(v.y + bias[c + 1]);
                v.z = softplusf(v.z + bias[c + 2]);
                v.w = softplusf(v.w + bias[c + 3]);
            }
            *(float4*)&C[(size_t)r * ldc + c] = v;
        }
    }
}

// ---------------- causal conv1d (D_CONV=4) + silu ----------------
__global__ void conv_silu_kernel(const float* __restrict__ xz,
                                 const float* __restrict__ cw,
                                 const float* __restrict__ cb,
                                 float* __restrict__ xc) {
    int idx = blockIdx.x * blockDim.x + threadIdx.x;   // over M_*DI
    if (idx >= M_ * DI) return;
    int d = idx & (DI - 1);
    int t = (idx >> 11) & (L_ - 1);
    int b = idx >> 22;

    const float4 w = ((const float4*)cw)[d];           // conv_w[d, 0..3]
    float acc = cb[d];
    size_t base = ((size_t)b * L_) * (size_t)(2 * DI) + d;

    if (t >= 3) {
        acc = fmaf(xz[base + (size_t)(t - 3) * (2 * DI)], w.x, acc);
        acc = fmaf(xz[base + (size_t)(t - 2) * (2 * DI)], w.y, acc);
        acc = fmaf(xz[base + (size_t)(t - 1) * (2 * DI)], w.z, acc);
        acc = fmaf(xz[base + (size_t)(t    ) * (2 * DI)], w.w, acc);
    } else {
        const float wk[4] = {w.x, w.y, w.z, w.w};
#pragma unroll
        for (int k = 0; k < 4; k++) {
            int tt = t + k - 3;
            if (tt >= 0) acc = fmaf(xz[base + (size_t)tt * (2 * DI)], wk[k], acc);
        }
    }
    xc[idx] = siluf(acc);
}

// ---------------- selective scan + gating ----------------
// warp per (b,d) channel; lane = state index (DS == 32).
// Every 32 steps: transpose 32t x 8d tile through smem, apply
// (y + u*D) * silu(z) and store coalesced into [b,t,d].
__global__ void scan_kernel(const float* __restrict__ delta,
                            const float* __restrict__ u,
                            const float* __restrict__ dbc,
                            const float* __restrict__ A_log,
                            const float* __restrict__ Dp,
                            const float* __restrict__ xz,
                            float* __restrict__ yout) {
    const int lane = threadIdx.x & 31;
    const int w    = threadIdx.x >> 5;            // 0..7
    const int d    = blockIdx.x * 8 + w;
    const int b    = blockIdx.y;

    __shared__ float sh[32][9];                   // [t][d], padded

    const float A2 = -expf(A_log[d * DS + lane]) * 1.4426950408889634f;
    float h = 0.f;
    float ybuf = 0.f;

    for (int t0 = 0; t0 < L_; t0 += 32) {
#pragma unroll 8
        for (int ti = 0; ti < 32; ti++) {
            const int t = t0 + ti;
            const size_t row = (size_t)(b * L_ + t);
            const float dl = delta[row * DI + d];
            const float uu = u[row * DI + d];
            const float Bv = dbc[row * 128 + 64 + lane];
            const float Cv = dbc[row * 128 + 96 + lane];
            const float dA = exp2f(dl * A2);
            h = fmaf(dA, h, dl * uu * Bv);
            float c = h * Cv;
#pragma unroll
            for (int o = 16; o; o >>= 1)
                c += __shfl_xor_sync(0xffffffffu, c, o);
            if (lane == ti) ybuf = c;
        }
        __syncthreads();
        sh[lane][w] = ybuf;
        __syncthreads();

        const int i  = threadIdx.x;
        const int tt = t0 + (i >> 3);
        const int dd = blockIdx.x * 8 + (i & 7);
        const size_t row = (size_t)(b * L_ + tt);
        const float yv = sh[i >> 3][i & 7];
        const float uu = u[row * DI + dd];
        const float zz = xz[row * (2 * DI) + DI + dd];
        const float Dv = Dp[dd];
        yout[row * DI + dd] = (yv + uu * Dv) * siluf(zz);
    }
}

// ---------------- in-place LayerNorm (row = 1024) ----------------
__global__ void ln_kernel(float* __restrict__ out,
                          const float* __restrict__ gamma,
                          const float* __restrict__ beta) {
    const int row = blockIdx.x;
    float4* p = (float4*)(out + (size_t)row * DM);
    const int i = threadIdx.x;                    // 0..255, 4 elems each

    float4 x = p[i];
    float s = x.x + x.y + x.z + x.w;
    float q = x.x * x.x + x.y * x.y + x.z * x.z + x.w * x.w;
#pragma unroll
    for (int o = 16; o; o >>= 1) {
        s += __shfl_xor_sync(0xffffffffu, s, o);
        q += __shfl_xor_sync(0xffffffffu, q, o);
    }
    __shared__ float rs[8], rq[8];
    if ((i & 31) == 0) { rs[i >> 5] = s; rq[i >> 5] = q; }
    __syncthreads();
    s = 0.f; q = 0.f;
#pragma unroll
    for (int k = 0; k < 8; k++) { s += rs[k]; q += rq[k]; }

    const float mu  = s * (1.f / DM);
    const float var = q * (1.f / DM) - mu * mu;
    const float inv = rsqrtf(var + LN_EPS);

    const float4 gg = ((const float4*)gamma)[i];
    const float4 bb = ((const float4*)beta)[i];
    x.x = (x.x - mu) * inv * gg.x + bb.x;
    x.y = (x.y - mu) * inv * gg.y + bb.y;
    x.z = (x.z - mu) * inv * gg.z + bb.z;
    x.w = (x.w - mu) * inv * gg.w + bb.w;
    p[i] = x;
}

// ---------------- launch ----------------
extern "C" void kernel_launch(void* const* d_in, const int* in_sizes, int n_in,
                              void* d_out, int out_size) {
    const float* x         = (const float*)d_in[0];
    const float* in_proj_w = (const float*)d_in[1];
    const float* conv_w    = (const float*)d_in[2];
    const float* conv_b    = (const float*)d_in[3];
    const float* x_proj_w  = (const float*)d_in[4];
    const float* dt_proj_w = (const float*)d_in[5];
    const float* dt_proj_b = (const float*)d_in[6];
    const float* A_log     = (const float*)d_in[7];
    const float* Dp        = (const float*)d_in[8];
    const float* out_proj_w= (const float*)d_in[9];
    const float* ln_gamma  = (const float*)d_in[10];
    const float* ln_beta   = (const float*)d_in[11];
    float* out = (float*)d_out;

    float *xz, *xc, *dbc, *delta, *yg;
    cudaGetSymbolAddress((void**)&xz,    g_xz);
    cudaGetSymbolAddress((void**)&xc,    g_xc);
    cudaGetSymbolAddress((void**)&dbc,   g_dbc);
    cudaGetSymbolAddress((void**)&delta, g_delta);
    cudaGetSymbolAddress((void**)&yg,    g_y);

    // 1) xz = x @ in_proj_w  [8192,4096]
    sgemm_kernel<128,128,16,8,8,0><<<dim3(2*DI/128, M_/128), 256>>>(
        x, in_proj_w, nullptr, xz, M_, 2*DI, DM, DM, 2*DI, 2*DI);

    // 2) conv + silu -> xc
    conv_silu_kernel<<<(M_*DI + 255)/256, 256>>>(xz, conv_w, conv_b, xc);

    // 3) dbc = xc @ x_proj_w  [8192,128]
    sgemm_kernel<64,64,16,4,4,0><<<dim3(128/64, M_/64), 256>>>(
        xc, x_proj_w, nullptr, dbc, M_, 128, DI, DI, 128, 128);

    // 4) delta = softplus(dt @ dt_proj_w + b)  [8192,2048]; dt = dbc[:, :64] (lda=128)
    sgemm_kernel<128,128,16,8,8,1><<<dim3(DI/128, M_/128), 256>>>(
        dbc, dt_proj_w, dt_proj_b, delta, M_, DI, DR, 128, DI, DI);

    // 5) selective scan + gating -> yg
    scan_kernel<<<dim3(DI/8, B_), 256>>>(delta, xc, dbc, A_log, Dp, xz, yg);

    // 6) out = yg @ out_proj_w  [8192,1024]
    sgemm_kernel<128,128,16,8,8,0><<<dim3(DM/128, M_/128), 256>>>(
        yg, out_proj_w, nullptr, out, M_, DM, DI, DI, DM, DM);

    // 7) in-place LayerNorm
    ln_kernel<<<M_, 256>>>(out, ln_gamma, ln_beta);
}

// round 2
// speedup vs baseline: 1.4189x; 1.4189x over previous
#include <cuda_runtime.h>
#include <cuda_bf16.h>
#include <cstdint>

// ---------------- problem dims (fixed) ----------------
#define B_   4
#define L_   2048
#define DM   1024      // d_model
#define DI   2048      // d_inner
#define DS   32        // d_state
#define DR   64        // dt_rank
#define M_   (B_ * L_) // 8192 rows
#define LN_EPS 1e-5f

// ---------------- scratch (device globals; no allocs allowed) ----------------
__device__ float g_xz[(size_t)M_ * 2 * DI];   // 8192 x 4096 (xi | z)
__device__ float g_xc[(size_t)M_ * DI];       // conv+silu output (u)
__device__ float g_dbc[(size_t)M_ * 128];     // dt(64) | B(32) | C(32)
__device__ float g_delta[(size_t)M_ * DI];    // softplus(dt @ dt_proj + b)
__device__ float g_y[(size_t)M_ * DI];        // gated scan output

// ---------------- helpers ----------------
__device__ __forceinline__ float siluf(float x) { return x / (1.f + expf(-x)); }
__device__ __forceinline__ float softplusf(float x) {
    return (x > 20.f) ? x : log1pf(expf(x));
}

// split fp32 pair -> packed bf16 hi + lo (low addr element in low 16 bits)
__device__ __forceinline__ void split2(float f0, float f1,
                                       uint32_t& hi, uint32_t& lo) {
    __nv_bfloat16 h0 = __float2bfloat16(f0);
    __nv_bfloat16 h1 = __float2bfloat16(f1);
    float r0 = f0 - __bfloat162float(h0);
    float r1 = f1 - __bfloat162float(h1);
    __nv_bfloat16 l0 = __float2bfloat16(r0);
    __nv_bfloat16 l1 = __float2bfloat16(r1);
    hi = (uint32_t)__bfloat16_as_ushort(h0) |
         ((uint32_t)__bfloat16_as_ushort(h1) << 16);
    lo = (uint32_t)__bfloat16_as_ushort(l0) |
         ((uint32_t)__bfloat16_as_ushort(l1) << 16);
}

__device__ __forceinline__ void ldm4(uint32_t* r, const uint32_t* p) {
    uint32_t addr = (uint32_t)__cvta_generic_to_shared(p);
    asm volatile("ldmatrix.sync.aligned.m8n8.x4.shared.b16 {%0,%1,%2,%3}, [%4];"
                 : "=r"(r[0]), "=r"(r[1]), "=r"(r[2]), "=r"(r[3]) : "r"(addr));
}

__device__ __forceinline__ void mma16816(float* c, const uint32_t* a,
                                         uint32_t b0, uint32_t b1) {
    asm volatile(
        "mma.sync.aligned.m16n8k16.row.col.f32.bf16.bf16.f32 "
        "{%0,%1,%2,%3}, {%4,%5,%6,%7}, {%8,%9}, {%0,%1,%2,%3};"
        : "+f"(c[0]), "+f"(c[1]), "+f"(c[2]), "+f"(c[3])
        : "r"(a[0]), "r"(a[1]), "r"(a[2]), "r"(a[3]), "r"(b0), "r"(b1));
}

// ---------------- bf16x3-split tensor-core GEMM ----------------
// C[M,N] = A[M,K](lda,f32) * B[K,N](ldb,f32), near-fp32 accuracy.
// Block tile 128x128, BK=16, 8 warps (2m x 4n), warp tile 64x32.
// Requires M%128==0, N%128==0, K%16==0.
template<int ACT>
__global__ void __launch_bounds__(256)
mma_gemm(const float* __restrict__ A, const float* __restrict__ Bm,
         const float* __restrict__ bias, float* __restrict__ C,
         int M, int N, int K, int lda, int ldb, int ldc) {
    // smem rows: 24 halves (48B) stride -> conflict-free ldmatrix, 12 u32/row
    __shared__ uint32_t sAhi[2][128 * 12];
    __shared__ uint32_t sAlo[2][128 * 12];
    __shared__ uint32_t sBhi[2][128 * 12];
    __shared__ uint32_t sBlo[2][128 * 12];

    const int tid    = threadIdx.x;
    const int lane   = tid & 31;
    const int wid    = tid >> 5;
    const int warp_m = wid >> 2;     // 0..1
    const int warp_n = wid & 3;      // 0..3
    const int bm = blockIdx.y * 128;
    const int bn = blockIdx.x * 128;

    float acc[4][4][4];
#pragma unroll
    for (int i = 0; i < 4; i++)
#pragma unroll
        for (int j = 0; j < 4; j++)
#pragma unroll
            for (int k = 0; k < 4; k++) acc[i][j][k] = 0.f;

    const int NK = K / 16;

    // A-load indexing: idx over 128 rows x 4 quads
    const int amr0 = tid >> 2,        akq0 = tid & 3;
    const int amr1 = (tid + 256) >> 2, akq1 = (tid + 256) & 3;
    // B-load indexing: kp 0..7 (k pair), nc 0..31 (n quad)
    const int bkp = tid & 7, bnc = tid >> 3;

    float4 ra0, ra1, rb0, rb1;

    auto load_g = [&](int k0) {
        ra0 = *(const float4*)&A[(size_t)(bm + amr0) * lda + k0 + akq0 * 4];
        ra1 = *(const float4*)&A[(size_t)(bm + amr1) * lda + k0 + akq1 * 4];
        rb0 = *(const float4*)&Bm[(size_t)(k0 + 2 * bkp) * ldb + bn + bnc * 4];
        rb1 = *(const float4*)&Bm[(size_t)(k0 + 2 * bkp + 1) * ldb + bn + bnc * 4];
    };
    auto store_s = [&](int buf) {
        uint32_t h, l;
        split2(ra0.x, ra0.y, h, l);
        sAhi[buf][amr0 * 12 + akq0 * 2 + 0] = h; sAlo[buf][amr0 * 12 + akq0 * 2 + 0] = l;
        split2(ra0.z, ra0.w, h, l);
        sAhi[buf][amr0 * 12 + akq0 * 2 + 1] = h; sAlo[buf][amr0 * 12 + akq0 * 2 + 1] = l;
        split2(ra1.x, ra1.y, h, l);
        sAhi[buf][amr1 * 12 + akq1 * 2 + 0] = h; sAlo[buf][amr1 * 12 + akq1 * 2 + 0] = l;
        split2(ra1.z, ra1.w, h, l);
        sAhi[buf][amr1 * 12 + akq1 * 2 + 1] = h; sAlo[buf][amr1 * 12 + akq1 * 2 + 1] = l;
        const float b0v[4] = {rb0.x, rb0.y, rb0.z, rb0.w};
        const float b1v[4] = {rb1.x, rb1.y, rb1.z, rb1.w};
#pragma unroll
        for (int j = 0; j < 4; j++) {
            split2(b0v[j], b1v[j], h, l);      // (k, k+1) pair for column n
            sBhi[buf][(bnc * 4 + j) * 12 + bkp] = h;
            sBlo[buf][(bnc * 4 + j) * 12 + bkp] = l;
        }
    };

    load_g(0);
    store_s(0);
    __syncthreads();

    for (int kt = 0; kt < NK; kt++) {
        const int buf = kt & 1;
        if (kt + 1 < NK) load_g((kt + 1) * 16);

        // fragment loads
        uint32_t aH[4][4], aL[4][4], bH[2][4], bL[2][4];
        const int rsel = lane & 15;
        const int koff = (lane >> 4) * 4;   // u32 offset (8 halves)
#pragma unroll
        for (int i = 0; i < 4; i++) {
            const int row = warp_m * 64 + i * 16 + rsel;
            ldm4(aH[i], &sAhi[buf][row * 12 + koff]);
            ldm4(aL[i], &sAlo[buf][row * 12 + koff]);
        }
#pragma unroll
        for (int j = 0; j < 2; j++) {
            const int nrow = warp_n * 32 + j * 16 + rsel;
            ldm4(bH[j], &sBhi[buf][nrow * 12 + koff]);
            ldm4(bL[j], &sBlo[buf][nrow * 12 + koff]);
        }
        // mma: 16 tiles x 3 passes
#pragma unroll
        for (int i = 0; i < 4; i++) {
#pragma unroll
            for (int t = 0; t < 4; t++) {
                const int j = t >> 1, s = t & 1;
                mma16816(acc[i][t], aH[i], bH[j][s], bH[j][s + 2]);
                mma16816(acc[i][t], aH[i], bL[j][s], bL[j][s + 2]);
                mma16816(acc[i][t], aL[i], bH[j][s], bH[j][s + 2]);
            }
        }
        if (kt + 1 < NK) store_s((kt + 1) & 1);
        __syncthreads();
    }

    // epilogue
    const int g  = lane >> 2;
    const int tq = lane & 3;
#pragma unroll
    for (int i = 0; i < 4; i++) {
        const int row0 = bm + warp_m * 64 + i * 16 + g;
#pragma unroll
        for (int t = 0; t < 4; t++) {
            const int col = bn + warp_n * 32 + t * 8 + 2 * tq;
            float2 v0 = make_float2(acc[i][t][0], acc[i][t][1]);
            float2 v1 = make_float2(acc[i][t][2], acc[i][t][3]);
            if (ACT == 1) {
                const float bb0 = bias[col], bb1 = bias[col + 1];
                v0.x = softplusf(v0.x + bb0); v0.y = softplusf(v0.y + bb1);
                v1.x = softplusf(v1.x + bb0); v1.y = softplusf(v1.y + bb1);
            }
            *(float2*)&C[(size_t)row0 * ldc + col] = v0;
            *(float2*)&C[(size_t)(row0 + 8) * ldc + col] = v1;
        }
    }
}

// ---------------- fp32 SGEMM (kept for the skinny N=128 GEMM) ----------------
template<int BM, int BN, int BK, int TM, int TN, int ACT>
__global__ void sgemm_kernel(const float* __restrict__ A,
                             const float* __restrict__ Bm,
                             const float* __restrict__ bias,
                             float* __restrict__ C,
                             int M, int N, int K, int lda, int ldb, int ldc) {
    constexpr int THREADS = (BM / TM) * (BN / TN);
    __shared__ float As[BK][BM];
    __shared__ float Bs[BK][BN];

    const int tid = threadIdx.x;
    const int bm = blockIdx.y * BM;
    const int bn = blockIdx.x * BN;
    const int tx = tid % (BN / TN);
    const int ty = tid / (BN / TN);

    float acc[TM][TN];
#pragma unroll
    for (int i = 0; i < TM; i++)
#pragma unroll
        for (int j = 0; j < TN; j++) acc[i][j] = 0.f;

    constexpr int A_ITERS = (BM * BK) / (THREADS * 4);
    constexpr int B_ITERS = (BK * BN) / (THREADS * 4);

    for (int k0 = 0; k0 < K; k0 += BK) {
#pragma unroll
        for (int i = 0; i < A_ITERS; i++) {
            int idx = tid + i * THREADS;
            int ar = idx / (BK / 4);
            int ac = (idx % (BK / 4)) * 4;
            float4 v = *(const float4*)&A[(size_t)(bm + ar) * lda + k0 + ac];
            As[ac + 0][ar] = v.x;
            As[ac + 1][ar] = v.y;
            As[ac + 2][ar] = v.z;
            As[ac + 3][ar] = v.w;
        }
#pragma unroll
        for (int i = 0; i < B_ITERS; i++) {
            int idx = tid + i * THREADS;
            int br = idx / (BN / 4);
            int bc = (idx % (BN / 4)) * 4;
            *(float4*)&Bs[br][bc] =
                *(const float4*)&Bm[(size_t)(k0 + br) * ldb + bn + bc];
        }
        __syncthreads();

#pragma unroll
        for (int k = 0; k < BK; k++) {
            float ra[TM], rb[TN];
#pragma unroll
            for (int i = 0; i < TM; i++) ra[i] = As[k][ty * TM + i];
#pragma unroll
            for (int j = 0; j < TN; j++) rb[j] = Bs[k][tx * TN + j];
#pragma unroll
            for (int i = 0; i < TM; i++)
#pragma unroll
                for (int j = 0; j < TN; j++)
                    acc[i][j] = fmaf(ra[i], rb[j], acc[i][j]);
        }
        __syncthreads();
    }

#pragma unroll
    for (int i = 0; i < TM; i++) {
        int r = bm + ty * TM + i;
#pragma unroll
        for (int j = 0; j < TN; j += 4) {
            int c = bn + tx * TN + j;
            float4 v;
            v.x = acc[i][j + 0];
            v.y = acc[i][j + 1];
            v.z = acc[i][j + 2];
            v.w = acc[i][j + 3];
            if (ACT == 1) {
                v.x = softplusf(v.x + bias[c + 0]);
                v.y = softplusf(v.y + bias[c + 1]);
                v.z = softplusf(v.z + bias[c + 2]);
                v.w = softplusf(v.w + bias[c + 3]);
            }
            *(float4*)&C[(size_t)r * ldc + c] = v;
        }
    }
}

// ---------------- causal conv1d (D_CONV=4) + silu ----------------
__global__ void conv_silu_kernel(const float* __restrict__ xz,
                                 const float* __restrict__ cw,
                                 const float* __restrict__ cb,
                                 float* __restrict__ xc) {
    int idx = blockIdx.x * blockDim.x + threadIdx.x;   // over M_*DI
    if (idx >= M_ * DI) return;
    int d = idx & (DI - 1);
    int t = (idx >> 11) & (L_ - 1);
    int b = idx >> 22;

    const float4 w = ((const float4*)cw)[d];           // conv_w[d, 0..3]
    float acc = cb[d];
    size_t base = ((size_t)b * L_) * (size_t)(2 * DI) + d;

    if (t >= 3) {
        acc = fmaf(xz[base + (size_t)(t - 3) * (2 * DI)], w.x, acc);
        acc = fmaf(xz[base + (size_t)(t - 2) * (2 * DI)], w.y, acc);
        acc = fmaf(xz[base + (size_t)(t - 1) * (2 * DI)], w.z, acc);
        acc = fmaf(xz[base + (size_t)(t    ) * (2 * DI)], w.w, acc);
    } else {
        const float wk[4] = {w.x, w.y, w.z, w.w};
#pragma unroll
        for (int k = 0; k < 4; k++) {
            int tt = t + k - 3;
            if (tt >= 0) acc = fmaf(xz[base + (size_t)tt * (2 * DI)], wk[k], acc);
        }
    }
    xc[idx] = siluf(acc);
}

// ---------------- selective scan + gating ----------------
__global__ void scan_kernel(const float* __restrict__ delta,
                            const float* __restrict__ u,
                            const float* __restrict__ dbc,
                            const float* __restrict__ A_log,
                            const float* __restrict__ Dp,
                            const float* __restrict__ xz,
                            float* __restrict__ yout) {
    const int lane = threadIdx.x & 31;
    const int w    = threadIdx.x >> 5;            // 0..7
    const int d    = blockIdx.x * 8 + w;
    const int b    = blockIdx.y;

    __shared__ float sh[32][9];                   // [t][d], padded

    const float A2 = -expf(A_log[d * DS + lane]) * 1.4426950408889634f;
    float h = 0.f;
    float ybuf = 0.f;

    for (int t0 = 0; t0 < L_; t0 += 32) {
#pragma unroll 8
        for (int ti = 0; ti < 32; ti++) {
            const int t = t0 + ti;
            const size_t row = (size_t)(b * L_ + t);
            const float dl = delta[row * DI + d];
            const float uu = u[row * DI + d];
            const float Bv = dbc[row * 128 + 64 + lane];
            const float Cv = dbc[row * 128 + 96 + lane];
            const float dA = exp2f(dl * A2);
            h = fmaf(dA, h, dl * uu * Bv);
            float c = h * Cv;
#pragma unroll
            for (int o = 16; o; o >>= 1)
                c += __shfl_xor_sync(0xffffffffu, c, o);
            if (lane == ti) ybuf = c;
        }
        __syncthreads();
        sh[lane][w] = ybuf;
        __syncthreads();

        const int i  = threadIdx.x;
        const int tt = t0 + (i >> 3);
        const int dd = blockIdx.x * 8 + (i & 7);
        const size_t row = (size_t)(b * L_ + tt);
        const float yv = sh[i >> 3][i & 7];
        const float uu = u[row * DI + dd];
        const float zz = xz[row * (2 * DI) + DI + dd];
        const float Dv = Dp[dd];
        yout[row * DI + dd] = (yv + uu * Dv) * siluf(zz);
    }
}

// ---------------- in-place LayerNorm (row = 1024) ----------------
__global__ void ln_kernel(float* __restrict__ out,
                          const float* __restrict__ gamma,
                          const float* __restrict__ beta) {
    const int row = blockIdx.x;
    float4* p = (float4*)(out + (size_t)row * DM);
    const int i = threadIdx.x;                    // 0..255, 4 elems each

    float4 x = p[i];
    float s = x.x + x.y + x.z + x.w;
    float q = x.x * x.x + x.y * x.y + x.z * x.z + x.w * x.w;
#pragma unroll
    for (int o = 16; o; o >>= 1) {
        s += __shfl_xor_sync(0xffffffffu, s, o);
        q += __shfl_xor_sync(0xffffffffu, q, o);
    }
    __shared__ float rs[8], rq[8];
    if ((i & 31) == 0) { rs[i >> 5] = s; rq[i >> 5] = q; }
    __syncthreads();
    s = 0.f; q = 0.f;
#pragma unroll
    for (int k = 0; k < 8; k++) { s += rs[k]; q += rq[k]; }

    const float mu  = s * (1.f / DM);
    const float var = q * (1.f / DM) - mu * mu;
    const float inv = rsqrtf(var + LN_EPS);

    const float4 gg = ((const float4*)gamma)[i];
    const float4 bb = ((const float4*)beta)[i];
    x.x = (x.x - mu) * inv * gg.x + bb.x;
    x.y = (x.y - mu) * inv * gg.y + bb.y;
    x.z = (x.z - mu) * inv * gg.z + bb.z;
    x.w = (x.w - mu) * inv * gg.w + bb.w;
    p[i] = x;
}

// ---------------- launch ----------------
extern "C" void kernel_launch(void* const* d_in, const int* in_sizes, int n_in,
                              void* d_out, int out_size) {
    const float* x         = (const float*)d_in[0];
    const float* in_proj_w = (const float*)d_in[1];
    const float* conv_w    = (const float*)d_in[2];
    const float* conv_b    = (const float*)d_in[3];
    const float* x_proj_w  = (const float*)d_in[4];
    const float* dt_proj_w = (const float*)d_in[5];
    const float* dt_proj_b = (const float*)d_in[6];
    const float* A_log     = (const float*)d_in[7];
    const float* Dp        = (const float*)d_in[8];
    const float* out_proj_w= (const float*)d_in[9];
    const float* ln_gamma  = (const float*)d_in[10];
    const float* ln_beta   = (const float*)d_in[11];
    float* out = (float*)d_out;

    float *xz, *xc, *dbc, *delta, *yg;
    cudaGetSymbolAddress((void**)&xz,    g_xz);
    cudaGetSymbolAddress((void**)&xc,    g_xc);
    cudaGetSymbolAddress((void**)&dbc,   g_dbc);
    cudaGetSymbolAddress((void**)&delta, g_delta);
    cudaGetSymbolAddress((void**)&yg,    g_y);

    // 1) xz = x @ in_proj_w  [8192,4096]  (tensor core, bf16x3)
    mma_gemm<0><<<dim3(2*DI/128, M_/128), 256>>>(
        x, in_proj_w, nullptr, xz, M_, 2*DI, DM, DM, 2*DI, 2*DI);

    // 2) conv + silu -> xc
    conv_silu_kernel<<<(M_*DI + 255)/256, 256>>>(xz, conv_w, conv_b, xc);

    // 3) dbc = xc @ x_proj_w  [8192,128]  (fp32, skinny N)
    sgemm_kernel<64,64,16,4,4,0><<<dim3(128/64, M_/64), 256>>>(
        xc, x_proj_w, nullptr, dbc, M_, 128, DI, DI, 128, 128);

    // 4) delta = softplus(dt @ dt_proj_w + b)  [8192,2048] (tensor core)
    mma_gemm<1><<<dim3(DI/128, M_/128), 256>>>(
        dbc, dt_proj_w, dt_proj_b, delta, M_, DI, DR, 128, DI, DI);

    // 5) selective scan + gating -> yg
    scan_kernel<<<dim3(DI/8, B_), 256>>>(delta, xc, dbc, A_log, Dp, xz, yg);

    // 6) out = yg @ out_proj_w  [8192,1024]  (tensor core)
    mma_gemm<0><<<dim3(DM/128, M_/128), 256>>>(
        yg, out_proj_w, nullptr, out, M_, DM, DI, DI, DM, DM);

    // 7) in-place LayerNorm
    ln_kernel<<<M_, 256>>>(out, ln_gamma, ln_beta);
}

// round 4
// speedup vs baseline: 1.5125x; 1.0659x over previous
#include <cuda_runtime.h>
#include <cuda_bf16.h>
#include <cstdint>

// ---------------- problem dims (fixed) ----------------
#define B_   4
#define L_   2048
#define DM   1024      // d_model
#define DI   2048      // d_inner
#define DS   32        // d_state
#define DR   64        // dt_rank
#define M_   (B_ * L_) // 8192 rows
#define LN_EPS 1e-5f

// ---------------- scratch (device globals; no allocs allowed) ----------------
__device__ __align__(256) float g_xz[(size_t)M_ * 2 * DI];   // xi | z  fp32
__device__ __align__(256) float g_xc[(size_t)M_ * DI];       // u fp32 (scan)
__device__ __align__(256) float g_dbc[(size_t)M_ * 128];     // dt|B|C fp32
__device__ __align__(256) float g_delta[(size_t)M_ * DI];    // softplus fp32

// bf16 hi/lo operand buffers
__device__ __align__(256) __nv_bfloat16 g_xhi[(size_t)M_ * DM],  g_xlo[(size_t)M_ * DM];
__device__ __align__(256) __nv_bfloat16 g_uhi[(size_t)M_ * DI],  g_ulo[(size_t)M_ * DI];
__device__ __align__(256) __nv_bfloat16 g_dthi[(size_t)M_ * DR], g_dtlo[(size_t)M_ * DR];
__device__ __align__(256) __nv_bfloat16 g_yhi[(size_t)M_ * DI],  g_ylo[(size_t)M_ * DI];
// weights, split + transposed to [N, K]
__device__ __align__(256) __nv_bfloat16 g_win_hi[(size_t)4096 * DM], g_win_lo[(size_t)4096 * DM];
__device__ __align__(256) __nv_bfloat16 g_wxp_hi[(size_t)128 * DI],  g_wxp_lo[(size_t)128 * DI];
__device__ __align__(256) __nv_bfloat16 g_wdt_hi[(size_t)DI * DR],   g_wdt_lo[(size_t)DI * DR];
__device__ __align__(256) __nv_bfloat16 g_wout_hi[(size_t)DM * DI],  g_wout_lo[(size_t)DM * DI];

// ---------------- helpers ----------------
__device__ __forceinline__ float siluf(float x) { return x / (1.f + expf(-x)); }
__device__ __forceinline__ float softplusf(float x) {
    return (x > 20.f) ? x : log1pf(expf(x));
}
__device__ __forceinline__ uint32_t smem_u32(const void* p) {
    return (uint32_t)__cvta_generic_to_shared(p);
}
__device__ __forceinline__ void cp16(uint32_t dst, const void* src) {
    asm volatile("cp.async.cg.shared.global [%0], [%1], 16;" :: "r"(dst), "l"(src));
}
__device__ __forceinline__ void ldm4(uint32_t* r, uint32_t addr) {
    asm volatile("ldmatrix.sync.aligned.m8n8.x4.shared.b16 {%0,%1,%2,%3}, [%4];"
                 : "=r"(r[0]), "=r"(r[1]), "=r"(r[2]), "=r"(r[3]) : "r"(addr));
}
__device__ __forceinline__ void mma16816(float* c, const uint32_t* a,
                                         uint32_t b0, uint32_t b1) {
    asm volatile(
        "mma.sync.aligned.m16n8k16.row.col.f32.bf16.bf16.f32 "
        "{%0,%1,%2,%3}, {%4,%5,%6,%7}, {%8,%9}, {%0,%1,%2,%3};"
        : "+f"(c[0]), "+f"(c[1]), "+f"(c[2]), "+f"(c[3])
        : "r"(a[0]), "r"(a[1]), "r"(a[2]), "r"(a[3]), "r"(b0), "r"(b1));
}

// ---------------- bf16x3 mma.sync GEMM, cp.async pipelined ----------------
// C[M,N] = Ahi/lo[M,K] x (Bhi/lo[N,K])^T, fp32 accum.
// Tile 128x128, BK=32. 512 threads = 16 warps (4m x 4n), warp tile 32x32.
// smem: 2 stages x 4 operands x (128 rows x 80B) = 81920 bytes.
#define ROWB 80
#define OPB  10240
#define STGB 40960
template<int ACT>
__global__ void __launch_bounds__(512)
mma_gemm(const __nv_bfloat16* __restrict__ Ahi, const __nv_bfloat16* __restrict__ Alo,
         const __nv_bfloat16* __restrict__ Bhi, const __nv_bfloat16* __restrict__ Blo,
         const float* __restrict__ bias, float* __restrict__ C,
         int K, int ldc) {
    extern __shared__ char smem[];
    const uint32_t sbase = smem_u32(smem);
    const int tid = threadIdx.x;
    const int lane = tid & 31, wid = tid >> 5;
    const int warp_m = wid >> 2, warp_n = wid & 3;
    const int bm = blockIdx.y * 128, bn = blockIdx.x * 128;

    float acc[2][4][4];
#pragma unroll
    for (int i = 0; i < 2; i++)
#pragma unroll
        for (int t = 0; t < 4; t++)
#pragma unroll
            for (int k = 0; k < 4; k++) acc[i][t][k] = 0.f;

    const int NK = K >> 5;
    // cp.async mapping: one 16B chunk per thread per operand per stage
    const int lr = tid >> 2, lc = tid & 3;
    const uint32_t soff = lr * ROWB + lc * 16;
    const __nv_bfloat16* pAh = Ahi + (size_t)(bm + lr) * K + lc * 8;
    const __nv_bfloat16* pAl = Alo + (size_t)(bm + lr) * K + lc * 8;
    const __nv_bfloat16* pBh = Bhi + (size_t)(bn + lr) * K + lc * 8;
    const __nv_bfloat16* pBl = Blo + (size_t)(bn + lr) * K + lc * 8;

    // prefetch stage 0
    cp16(sbase + soff,             pAh);
    cp16(sbase + OPB + soff,       pAl);
    cp16(sbase + 2 * OPB + soff,   pBh);
    cp16(sbase + 3 * OPB + soff,   pBl);
    asm volatile("cp.async.commit_group;" ::: "memory");

    const int rsel = lane & 15, ksel = lane >> 4;

    for (int kt = 0; kt < NK; kt++) {
        if (kt + 1 < NK) {
            const uint32_t sb = sbase + ((kt + 1) & 1) * STGB;
            const int k0 = (kt + 1) << 5;
            cp16(sb + soff,           pAh + k0);
            cp16(sb + OPB + soff,     pAl + k0);
            cp16(sb + 2 * OPB + soff, pBh + k0);
            cp16(sb + 3 * OPB + soff, pBl + k0);
        }
        asm volatile("cp.async.commit_group;" ::: "memory");
        asm volatile("cp.async.wait_group 1;" ::: "memory");
        __syncthreads();

        const uint32_t sb = sbase + (kt & 1) * STGB;
#pragma unroll
        for (int ks = 0; ks < 2; ks++) {
            uint32_t aH[2][4], aL[2][4], bH[2][4], bL[2][4];
            const uint32_t ko = (uint32_t)(ks * 2 + ksel) * 16;
#pragma unroll
            for (int i = 0; i < 2; i++) {
                const uint32_t off = (uint32_t)(warp_m * 32 + i * 16 + rsel) * ROWB + ko;
                ldm4(aH[i], sb + off);
                ldm4(aL[i], sb + OPB + off);
            }
#pragma unroll
            for (int j = 0; j < 2; j++) {
                const uint32_t off = (uint32_t)(warp_n * 32 + j * 16 + rsel) * ROWB + ko;
                ldm4(bH[j], sb + 2 * OPB + off);
                ldm4(bL[j], sb + 3 * OPB + off);
            }
#pragma unroll
            for (int i = 0; i < 2; i++)
#pragma unroll
                for (int t = 0; t < 4; t++) {
                    const int j = t >> 1, s2 = t & 1;
                    mma16816(acc[i][t], aH[i], bH[j][s2], bH[j][s2 + 2]);
                    mma16816(acc[i][t], aH[i], bL[j][s2], bL[j][s2 + 2]);
                    mma16816(acc[i][t], aL[i], bH[j][s2], bH[j][s2 + 2]);
                }
        }
        __syncthreads();
    }

    // epilogue
    const int g  = lane >> 2;
    const int tq = lane & 3;
#pragma unroll
    for (int i = 0; i < 2; i++) {
        const int row0 = bm + warp_m * 32 + i * 16 + g;
#pragma unroll
        for (int t = 0; t < 4; t++) {
            const int col = bn + warp_n * 32 + t * 8 + 2 * tq;
            float2 v0 = make_float2(acc[i][t][0], acc[i][t][1]);
            float2 v1 = make_float2(acc[i][t][2], acc[i][t][3]);
            if (ACT == 1) {
                const float bb0 = bias[col], bb1 = bias[col + 1];
                v0.x = softplusf(v0.x + bb0); v0.y = softplusf(v0.y + bb1);
                v1.x = softplusf(v1.x + bb0); v1.y = softplusf(v1.y + bb1);
            }
            *(float2*)&C[(size_t)row0 * ldc + col] = v0;
            *(float2*)&C[(size_t)(row0 + 8) * ldc + col] = v1;
        }
    }
}

// ---------------- split / transpose-split kernels ----------------
__device__ __forceinline__ uint32_t pack_split(float f0, float f1, uint32_t& lo) {
    __nv_bfloat16 h0 = __float2bfloat16(f0), h1 = __float2bfloat16(f1);
    __nv_bfloat16 l0 = __float2bfloat16(f0 - __bfloat162float(h0));
    __nv_bfloat16 l1 = __float2bfloat16(f1 - __bfloat162float(h1));
    lo = (uint32_t)__bfloat16_as_ushort(l0) | ((uint32_t)__bfloat16_as_ushort(l1) << 16);
    return (uint32_t)__bfloat16_as_ushort(h0) | ((uint32_t)__bfloat16_as_ushort(h1) << 16);
}

__global__ void split_kernel(const float2* __restrict__ src,
                             uint32_t* __restrict__ hi, uint32_t* __restrict__ lo,
                             int n2) {
    int i = blockIdx.x * blockDim.x + threadIdx.x;
    if (i >= n2) return;
    float2 f = src[i];
    uint32_t l; uint32_t h = pack_split(f.x, f.y, l);
    hi[i] = h; lo[i] = l;
}

// src [K,N] fp32 -> dst hi/lo [N,K] bf16
__global__ void tsplit_kernel(const float* __restrict__ src,
                              __nv_bfloat16* __restrict__ hi,
                              __nv_bfloat16* __restrict__ lo, int K, int N) {
    __shared__ float t[32][33];
    const int k0 = blockIdx.y * 32, n0 = blockIdx.x * 32;
    const int tx = threadIdx.x, ty = threadIdx.y;
#pragma unroll
    for (int i = 0; i < 32; i += 8)
        t[ty + i][tx] = src[(size_t)(k0 + ty + i) * N + n0 + tx];
    __syncthreads();
#pragma unroll
    for (int i = 0; i < 32; i += 8) {
        float f = t[tx][ty + i];
        __nv_bfloat16 h = __float2bfloat16(f);
        size_t o = (size_t)(n0 + ty + i) * K + k0 + tx;
        hi[o] = h;
        lo[o] = __float2bfloat16(f - __bfloat162float(h));
    }
}

// extract dt = dbc[:, 0:64] -> hi/lo [M,64]
__global__ void dtsplit_kernel(const float* __restrict__ dbc,
                               uint32_t* __restrict__ hi, uint32_t* __restrict__ lo) {
    int i = blockIdx.x * blockDim.x + threadIdx.x;   // over M_*32
    if (i >= M_ * 32) return;
    const int r = i >> 5, c2 = i & 31;
    float2 f = ((const float2*)(dbc + (size_t)r * 128))[c2];
    uint32_t l; uint32_t h = pack_split(f.x, f.y, l);
    hi[(size_t)r * 32 + c2] = h;
    lo[(size_t)r * 32 + c2] = l;
}

// ---------------- causal conv1d (D_CONV=4) + silu (+ bf16 split) ----------------
__global__ void conv_silu_kernel(const float* __restrict__ xz,
                                 const float* __restrict__ cw,
                                 const float* __restrict__ cb,
                                 float* __restrict__ xc,
                                 __nv_bfloat16* __restrict__ uhi,
                                 __nv_bfloat16* __restrict__ ulo) {
    int idx = blockIdx.x * blockDim.x + threadIdx.x;   // over M_*DI
    if (idx >= M_ * DI) return;
    int d = idx & (DI - 1);
    int t = (idx >> 11) & (L_ - 1);
    int b = idx >> 22;

    const float4 w = ((const float4*)cw)[d];
    float acc = cb[d];
    size_t base = ((size_t)b * L_) * (size_t)(2 * DI) + d;

    if (t >= 3) {
        acc = fmaf(xz[base + (size_t)(t - 3) * (2 * DI)], w.x, acc);
        acc = fmaf(xz[base + (size_t)(t - 2) * (2 * DI)], w.y, acc);
        acc = fmaf(xz[base + (size_t)(t - 1) * (2 * DI)], w.z, acc);
        acc = fmaf(xz[base + (size_t)(t    ) * (2 * DI)], w.w, acc);
    } else {
        const float wk[4] = {w.x, w.y, w.z, w.w};
#pragma unroll
        for (int k = 0; k < 4; k++) {
            int tt = t + k - 3;
            if (tt >= 0) acc = fmaf(xz[base + (size_t)tt * (2 * DI)], wk[k], acc);
        }
    }
    const float s = siluf(acc);
    xc[idx] = s;
    __nv_bfloat16 h = __float2bfloat16(s);
    uhi[idx] = h;
    ulo[idx] = __float2bfloat16(s - __bfloat162float(h));
}

// ---------------- selective scan + gating (writes bf16 hi/lo) ----------------
__global__ void scan_kernel(const float* __restrict__ delta,
                            const float* __restrict__ u,
                            const float* __restrict__ dbc,
                            const float* __restrict__ A_log,
                            const float* __restrict__ Dp,
                            const float* __restrict__ xz,
                            __nv_bfloat16* __restrict__ yhi,
                            __nv_bfloat16* __restrict__ ylo) {
    const int lane = threadIdx.x & 31;
    const int w    = threadIdx.x >> 5;            // 0..7
    const int d    = blockIdx.x * 8 + w;
    const int b    = blockIdx.y;

    __shared__ float sh[32][9];

    const float A2 = -expf(A_log[d * DS + lane]) * 1.4426950408889634f;
    float h = 0.f;
    float ybuf = 0.f;

    for (int t0 = 0; t0 < L_; t0 += 32) {
#pragma unroll 8
        for (int ti = 0; ti < 32; ti++) {
            const int t = t0 + ti;
            const size_t row = (size_t)(b * L_ + t);
            const float dl = delta[row * DI + d];
            const float uu = u[row * DI + d];
            const float Bv = dbc[row * 128 + 64 + lane];
            const float Cv = dbc[row * 128 + 96 + lane];
            const float dA = exp2f(dl * A2);
            h = fmaf(dA, h, dl * uu * Bv);
            float c = h * Cv;
#pragma unroll
            for (int o = 16; o; o >>= 1)
                c += __shfl_xor_sync(0xffffffffu, c, o);
            if (lane == ti) ybuf = c;
        }
        __syncthreads();
        sh[lane][w] = ybuf;
        __syncthreads();

        const int i  = threadIdx.x;
        const int tt = t0 + (i >> 3);
        const int dd = blockIdx.x * 8 + (i & 7);
        const size_t row = (size_t)(b * L_ + tt);
        const float yv = sh[i >> 3][i & 7];
        const float uu = u[row * DI + dd];
        const float zz = xz[row * (2 * DI) + DI + dd];
        const float Dv = Dp[dd];
        const float yf = (yv + uu * Dv) * siluf(zz);
        __nv_bfloat16 hh = __float2bfloat16(yf);
        yhi[row * DI + dd] = hh;
        ylo[row * DI + dd] = __float2bfloat16(yf - __bfloat162float(hh));
    }
}

// ---------------- in-place LayerNorm (row = 1024) ----------------
__global__ void ln_kernel(float* __restrict__ out,
                          const float* __restrict__ gamma,
                          const float* __restrict__ beta) {
    const int row = blockIdx.x;
    float4* p = (float4*)(out + (size_t)row * DM);
    const int i = threadIdx.x;

    float4 x = p[i];
    float s = x.x + x.y + x.z + x.w;
    float q = x.x * x.x + x.y * x.y + x.z * x.z + x.w * x.w;
#pragma unroll
    for (int o = 16; o; o >>= 1) {
        s += __shfl_xor_sync(0xffffffffu, s, o);
        q += __shfl_xor_sync(0xffffffffu, q, o);
    }
    __shared__ float rs[8], rq[8];
    if ((i & 31) == 0) { rs[i >> 5] = s; rq[i >> 5] = q; }
    __syncthreads();
    s = 0.f; q = 0.f;
#pragma unroll
    for (int k = 0; k < 8; k++) { s += rs[k]; q += rq[k]; }

    const float mu  = s * (1.f / DM);
    const float var = q * (1.f / DM) - mu * mu;
    const float inv = rsqrtf(var + LN_EPS);

    const float4 gg = ((const float4*)gamma)[i];
    const float4 bb = ((const float4*)beta)[i];
    x.x = (x.x - mu) * inv * gg.x + bb.x;
    x.y = (x.y - mu) * inv * gg.y + bb.y;
    x.z = (x.z - mu) * inv * gg.z + bb.z;
    x.w = (x.w - mu) * inv * gg.w + bb.w;
    p[i] = x;
}

// ---------------- launch ----------------
extern "C" void kernel_launch(void* const* d_in, const int* in_sizes, int n_in,
                              void* d_out, int out_size) {
    (void)in_sizes; (void)n_in; (void)out_size;
    const float* x         = (const float*)d_in[0];
    const float* in_proj_w = (const float*)d_in[1];
    const float* conv_w    = (const float*)d_in[2];
    const float* conv_b    = (const float*)d_in[3];
    const float* x_proj_w  = (const float*)d_in[4];
    const float* dt_proj_w = (const float*)d_in[5];
    const float* dt_proj_b = (const float*)d_in[6];
    const float* A_log     = (const float*)d_in[7];
    const float* Dp        = (const float*)d_in[8];
    const float* out_proj_w= (const float*)d_in[9];
    const float* ln_gamma  = (const float*)d_in[10];
    const float* ln_beta   = (const float*)d_in[11];
    float* out = (float*)d_out;

    float *xz, *xc, *dbc, *delta;
    __nv_bfloat16 *xhi, *xlo, *uhi, *ulo, *dthi, *dtlo, *yhi, *ylo;
    __nv_bfloat16 *winh, *winl, *wxph, *wxpl, *wdth, *wdtl, *wouth, *woutl;
    cudaGetSymbolAddress((void**)&xz,    g_xz);
    cudaGetSymbolAddress((void**)&xc,    g_xc);
    cudaGetSymbolAddress((void**)&dbc,   g_dbc);
    cudaGetSymbolAddress((void**)&delta, g_delta);
    cudaGetSymbolAddress((void**)&xhi,   g_xhi);
    cudaGetSymbolAddress((void**)&xlo,   g_xlo);
    cudaGetSymbolAddress((void**)&uhi,   g_uhi);
    cudaGetSymbolAddress((void**)&ulo,   g_ulo);
    cudaGetSymbolAddress((void**)&dthi,  g_dthi);
    cudaGetSymbolAddress((void**)&dtlo,  g_dtlo);
    cudaGetSymbolAddress((void**)&yhi,   g_yhi);
    cudaGetSymbolAddress((void**)&ylo,   g_ylo);
    cudaGetSymbolAddress((void**)&winh,  g_win_hi);
    cudaGetSymbolAddress((void**)&winl,  g_win_lo);
    cudaGetSymbolAddress((void**)&wxph,  g_wxp_hi);
    cudaGetSymbolAddress((void**)&wxpl,  g_wxp_lo);
    cudaGetSymbolAddress((void**)&wdth,  g_wdt_hi);
    cudaGetSymbolAddress((void**)&wdtl,  g_wdt_lo);
    cudaGetSymbolAddress((void**)&wouth, g_wout_hi);
    cudaGetSymbolAddress((void**)&woutl, g_wout_lo);

    constexpr int SMEM = 2 * STGB;   // 81920
    cudaFuncSetAttribute(mma_gemm<0>, cudaFuncAttributeMaxDynamicSharedMemorySize, SMEM);
    cudaFuncSetAttribute(mma_gemm<1>, cudaFuncAttributeMaxDynamicSharedMemorySize, SMEM);

    // 0) weight split+transpose  ([K,N] fp32 -> [N,K] bf16 hi/lo)
    tsplit_kernel<<<dim3(4096/32, DM/32), dim3(32,8)>>>(in_proj_w,  winh,  winl,  DM, 4096);
    tsplit_kernel<<<dim3(128/32,  DI/32), dim3(32,8)>>>(x_proj_w,   wxph,  wxpl,  DI, 128);
    tsplit_kernel<<<dim3(DI/32,   DR/32), dim3(32,8)>>>(dt_proj_w,  wdth,  wdtl,  DR, DI);
    tsplit_kernel<<<dim3(DM/32,   DI/32), dim3(32,8)>>>(out_proj_w, wouth, woutl, DI, DM);
    // 0b) x split
    split_kernel<<<(M_*DM/2 + 255)/256, 256>>>((const float2*)x, (uint32_t*)xhi, (uint32_t*)xlo, M_*DM/2);

    // 1) xz = x @ in_proj_w  [8192,4096]
    mma_gemm<0><<<dim3(4096/128, M_/128), 512, SMEM>>>(
        xhi, xlo, winh, winl, nullptr, xz, DM, 4096);

    // 2) conv + silu -> xc (fp32) + uhi/ulo
    conv_silu_kernel<<<(M_*DI + 255)/256, 256>>>(xz, conv_w, conv_b, xc, uhi, ulo);

    // 3) dbc = u @ x_proj_w  [8192,128]
    mma_gemm<0><<<dim3(1, M_/128), 512, SMEM>>>(
        uhi, ulo, wxph, wxpl, nullptr, dbc, DI, 128);

    // 3b) dt split
    dtsplit_kernel<<<(M_*32 + 255)/256, 256>>>(dbc, (uint32_t*)dthi, (uint32_t*)dtlo);

    // 4) delta = softplus(dt @ dt_proj_w + b)  [8192,2048]
    mma_gemm<1><<<dim3(DI/128, M_/128), 512, SMEM>>>(
        dthi, dtlo, wdth, wdtl, dt_proj_b, delta, DR, DI);

    // 5) selective scan + gating -> yhi/ylo
    scan_kernel<<<dim3(DI/8, B_), 256>>>(delta, xc, dbc, A_log, Dp, xz, yhi, ylo);

    // 6) out = y @ out_proj_w  [8192,1024]
    mma_gemm<0><<<dim3(DM/128, M_/128), 512, SMEM>>>(
        yhi, ylo, wouth, woutl, nullptr, out, DI, DM);

    // 7) in-place LayerNorm
    ln_kernel<<<M_, 256>>>(out, ln_gamma, ln_beta);
}

// round 5
// speedup vs baseline: 2.1793x; 1.4409x over previous
#include <cuda_runtime.h>
#include <cuda_fp16.h>
#include <cstdint>

// ---------------- problem dims (fixed) ----------------
#define B_   4
#define L_   2048
#define DM   1024      // d_model
#define DI   2048      // d_inner
#define DS   32        // d_state
#define DR   64        // dt_rank
#define M_   (B_ * L_) // 8192 rows
#define LN_EPS 1e-5f

// ---------------- scratch (device globals; no allocs allowed) ----------------
__device__ __align__(256) float g_xz[(size_t)M_ * 2 * DI];   // xi | z  fp32
__device__ __align__(256) float g_xc[(size_t)M_ * DI];       // u fp32 (scan)
__device__ __align__(256) float g_dbc[(size_t)M_ * 128];     // dt|B|C fp32
__device__ __align__(256) float g_delta[(size_t)M_ * DI];    // softplus fp32

// fp16 hi/lo activation operands
__device__ __align__(256) half g_xhi[(size_t)M_ * DM],  g_xlo[(size_t)M_ * DM];
__device__ __align__(256) half g_uhi[(size_t)M_ * DI],  g_ulo[(size_t)M_ * DI];
__device__ __align__(256) half g_dthi[(size_t)M_ * DR], g_dtlo[(size_t)M_ * DR];
__device__ __align__(256) half g_yhi[(size_t)M_ * DI],  g_ylo[(size_t)M_ * DI];
// weights, converted + transposed to [N, K] fp16 (hi only)
__device__ __align__(256) half g_win[(size_t)4096 * DM];
__device__ __align__(256) half g_wxp[(size_t)128 * DI];
__device__ __align__(256) half g_wdt[(size_t)DI * DR];
__device__ __align__(256) half g_wout[(size_t)DM * DI];

// ---------------- helpers ----------------
__device__ __forceinline__ float siluf(float x) { return x / (1.f + expf(-x)); }
__device__ __forceinline__ float softplusf(float x) {
    return (x > 20.f) ? x : log1pf(expf(x));
}
__device__ __forceinline__ float ex2f(float x) {
    float y; asm("ex2.approx.ftz.f32 %0, %1;" : "=f"(y) : "f"(x)); return y;
}
__device__ __forceinline__ uint32_t smem_u32(const void* p) {
    return (uint32_t)__cvta_generic_to_shared(p);
}
__device__ __forceinline__ void cp16(uint32_t dst, const void* src) {
    asm volatile("cp.async.cg.shared.global [%0], [%1], 16;" :: "r"(dst), "l"(src));
}
__device__ __forceinline__ void ldm4(uint32_t* r, uint32_t addr) {
    asm volatile("ldmatrix.sync.aligned.m8n8.x4.shared.b16 {%0,%1,%2,%3}, [%4];"
                 : "=r"(r[0]), "=r"(r[1]), "=r"(r[2]), "=r"(r[3]) : "r"(addr));
}
__device__ __forceinline__ void mma16816(float* c, const uint32_t* a,
                                         uint32_t b0, uint32_t b1) {
    asm volatile(
        "mma.sync.aligned.m16n8k16.row.col.f32.f16.f16.f32 "
        "{%0,%1,%2,%3}, {%4,%5,%6,%7}, {%8,%9}, {%0,%1,%2,%3};"
        : "+f"(c[0]), "+f"(c[1]), "+f"(c[2]), "+f"(c[3])
        : "r"(a[0]), "r"(a[1]), "r"(a[2]), "r"(a[3]), "r"(b0), "r"(b1));
}
__device__ __forceinline__ void split_store_dt(half* hi, half* lo,
                                               int row, int col, float v) {
    half h = __float2half(v);
    hi[(size_t)row * DR + col] = h;
    lo[(size_t)row * DR + col] = __float2half(v - __half2float(h));
}

// ---------------- fp16x2 mma.sync GEMM, cp.async pipelined ----------------
// C[M,N] = (Ahi+Alo)[M,K] x (Bh[N,K])^T, fp32 accum, 2 mma passes.
// Tile 128xBN, BK=32. WN = BN/32 warp cols, 4 warp rows, warp tile 32x32.
// ACT: 0 none, 1 softplus(+bias), 2 also emit fp16 split of cols 0..63 (dt).
#define ROWB 80
#define APB  10240            // 128 rows * 80B
template<int BN, int ACT>
__global__ void __launch_bounds__(128 * (BN / 32))
mma_gemm(const half* __restrict__ Ahi, const half* __restrict__ Alo,
         const half* __restrict__ Bh,
         const float* __restrict__ bias, float* __restrict__ C,
         half* __restrict__ dthi, half* __restrict__ dtlo,
         int K, int ldc) {
    constexpr int WN  = BN / 32;
    constexpr int T   = 128 * WN;
    constexpr int BPB = BN * ROWB;
    constexpr int STG = 2 * APB + BPB;

    extern __shared__ char smem[];
    const uint32_t sbase = smem_u32(smem);
    const int tid = threadIdx.x;
    const int lane = tid & 31, wid = tid >> 5;
    const int warp_m = wid / WN, warp_n = wid % WN;
    const int bm = blockIdx.y * 128, bn = blockIdx.x * BN;

    float acc[2][4][4];
#pragma unroll
    for (int i = 0; i < 2; i++)
#pragma unroll
        for (int t = 0; t < 4; t++)
#pragma unroll
            for (int k = 0; k < 4; k++) acc[i][t][k] = 0.f;

    const int NK = K >> 5;

    // stage loader: A(hi,lo): 128 rows x 4 x 16B; B: BN rows x 4 x 16B
    auto stage_load = [&](int kt, uint32_t sb) {
        const int k0 = kt << 5;
#pragma unroll
        for (int ii = 0; ii < 512 / T; ii++) {
            const int i = tid + ii * T;
            const int r = i >> 2, c = i & 3;
            const uint32_t so = (uint32_t)(r * ROWB + c * 16);
            cp16(sb + so,       Ahi + (size_t)(bm + r) * K + k0 + c * 8);
            cp16(sb + APB + so, Alo + (size_t)(bm + r) * K + k0 + c * 8);
        }
#pragma unroll
        for (int ii = 0; ii < (BN * 4) / T; ii++) {
            const int i = tid + ii * T;
            const int r = i >> 2, c = i & 3;
            cp16(sb + 2 * APB + (uint32_t)(r * ROWB + c * 16),
                 Bh + (size_t)(bn + r) * K + k0 + c * 8);
        }
    };

    stage_load(0, sbase);
    asm volatile("cp.async.commit_group;" ::: "memory");

    const int rsel = lane & 15, ksel = lane >> 4;

    for (int kt = 0; kt < NK; kt++) {
        if (kt + 1 < NK)
            stage_load(kt + 1, sbase + ((kt + 1) & 1) * STG);
        asm volatile("cp.async.commit_group;" ::: "memory");
        asm volatile("cp.async.wait_group 1;" ::: "memory");
        __syncthreads();

        const uint32_t sb = sbase + (kt & 1) * STG;
#pragma unroll
        for (int ks = 0; ks < 2; ks++) {
            uint32_t aH[2][4], aL[2][4], bH[2][4];
            const uint32_t ko = (uint32_t)(ks * 2 + ksel) * 16;
#pragma unroll
            for (int i = 0; i < 2; i++) {
                const uint32_t off = (uint32_t)(warp_m * 32 + i * 16 + rsel) * ROWB + ko;
                ldm4(aH[i], sb + off);
                ldm4(aL[i], sb + APB + off);
            }
#pragma unroll
            for (int j = 0; j < 2; j++) {
                const uint32_t off = (uint32_t)(warp_n * 32 + j * 16 + rsel) * ROWB + ko;
                ldm4(bH[j], sb + 2 * APB + off);
            }
#pragma unroll
            for (int i = 0; i < 2; i++)
#pragma unroll
                for (int t = 0; t < 4; t++) {
                    const int j = t >> 1, s2 = t & 1;
                    mma16816(acc[i][t], aH[i], bH[j][s2], bH[j][s2 + 2]);
                    mma16816(acc[i][t], aL[i], bH[j][s2], bH[j][s2 + 2]);
                }
        }
        __syncthreads();
    }

    // epilogue
    const int g  = lane >> 2;
    const int tq = lane & 3;
#pragma unroll
    for (int i = 0; i < 2; i++) {
        const int row0 = bm + warp_m * 32 + i * 16 + g;
#pragma unroll
        for (int t = 0; t < 4; t++) {
            const int col = bn + warp_n * 32 + t * 8 + 2 * tq;
            float2 v0 = make_float2(acc[i][t][0], acc[i][t][1]);
            float2 v1 = make_float2(acc[i][t][2], acc[i][t][3]);
            if (ACT == 1) {
                const float bb0 = bias[col], bb1 = bias[col + 1];
                v0.x = softplusf(v0.x + bb0); v0.y = softplusf(v0.y + bb1);
                v1.x = softplusf(v1.x + bb0); v1.y = softplusf(v1.y + bb1);
            }
            *(float2*)&C[(size_t)row0 * ldc + col] = v0;
            *(float2*)&C[(size_t)(row0 + 8) * ldc + col] = v1;
            if (ACT == 2 && blockIdx.x == 0) {   // cols 0..63 = dt
                split_store_dt(dthi, dtlo, row0,     col,     v0.x);
                split_store_dt(dthi, dtlo, row0,     col + 1, v0.y);
                split_store_dt(dthi, dtlo, row0 + 8, col,     v1.x);
                split_store_dt(dthi, dtlo, row0 + 8, col + 1, v1.y);
            }
        }
    }
}

// ---------------- producers: fp16 split / convert ----------------
__global__ void split_kernel(const float2* __restrict__ src,
                             uint32_t* __restrict__ hi, uint32_t* __restrict__ lo,
                             int n2) {
    int i = blockIdx.x * blockDim.x + threadIdx.x;
    if (i >= n2) return;
    float2 f = src[i];
    half h0 = __float2half(f.x), h1 = __float2half(f.y);
    half l0 = __float2half(f.x - __half2float(h0));
    half l1 = __float2half(f.y - __half2float(h1));
    hi[i] = (uint32_t)__half_as_ushort(h0) | ((uint32_t)__half_as_ushort(h1) << 16);
    lo[i] = (uint32_t)__half_as_ushort(l0) | ((uint32_t)__half_as_ushort(l1) << 16);
}

// weights: src [K,N] fp32 -> dst [N,K] fp16
__global__ void tconv_kernel(const float* __restrict__ src,
                             half* __restrict__ dst, int K, int N) {
    __shared__ float t[32][33];
    const int k0 = blockIdx.y * 32, n0 = blockIdx.x * 32;
    const int tx = threadIdx.x, ty = threadIdx.y;
#pragma unroll
    for (int i = 0; i < 32; i += 8)
        t[ty + i][tx] = src[(size_t)(k0 + ty + i) * N + n0 + tx];
    __syncthreads();
#pragma unroll
    for (int i = 0; i < 32; i += 8)
        dst[(size_t)(n0 + ty + i) * K + k0 + tx] = __float2half(t[tx][ty + i]);
}

// ---------------- causal conv1d (D_CONV=4) + silu (+ fp16 split) ----------------
__global__ void conv_silu_kernel(const float* __restrict__ xz,
                                 const float* __restrict__ cw,
                                 const float* __restrict__ cb,
                                 float* __restrict__ xc,
                                 half* __restrict__ uhi,
                                 half* __restrict__ ulo) {
    int idx = blockIdx.x * blockDim.x + threadIdx.x;   // over M_*DI
    if (idx >= M_ * DI) return;
    int d = idx & (DI - 1);
    int t = (idx >> 11) & (L_ - 1);
    int b = idx >> 22;

    const float4 w = ((const float4*)cw)[d];
    float acc = cb[d];
    size_t base = ((size_t)b * L_) * (size_t)(2 * DI) + d;

    if (t >= 3) {
        acc = fmaf(xz[base + (size_t)(t - 3) * (2 * DI)], w.x, acc);
        acc = fmaf(xz[base + (size_t)(t - 2) * (2 * DI)], w.y, acc);
        acc = fmaf(xz[base + (size_t)(t - 1) * (2 * DI)], w.z, acc);
        acc = fmaf(xz[base + (size_t)(t    ) * (2 * DI)], w.w, acc);
    } else {
        const float wk[4] = {w.x, w.y, w.z, w.w};
#pragma unroll
        for (int k = 0; k < 4; k++) {
            int tt = t + k - 3;
            if (tt >= 0) acc = fmaf(xz[base + (size_t)tt * (2 * DI)], wk[k], acc);
        }
    }
    const float s = siluf(acc);
    xc[idx] = s;
    half h = __float2half(s);
    uhi[idx] = h;
    ulo[idx] = __float2half(s - __half2float(h));
}

// ---------------- selective scan + gating ----------------
// Warp per (b,d). lane = state. 32-step register blocks; one 31-shfl
// butterfly multi-reduce delivers y_{t0+lane} to lane.
__global__ void scan_kernel(const float* __restrict__ delta,
                            const float* __restrict__ u,
                            const float* __restrict__ dbc,
                            const float* __restrict__ A_log,
                            const float* __restrict__ Dp,
                            const float* __restrict__ xz,
                            half* __restrict__ yhi,
                            half* __restrict__ ylo) {
    const int lane = threadIdx.x & 31;
    const int w    = threadIdx.x >> 5;            // 0..7
    const int d    = blockIdx.x * 8 + w;
    const int b    = blockIdx.y;

    __shared__ float sh[32][9];                   // [t][d], padded

    const float A2 = -expf(A_log[d * DS + lane]) * 1.4426950408889634f;
    float h = 0.f;

    for (int t0 = 0; t0 < L_; t0 += 32) {
        float v[32];
#pragma unroll
        for (int ti = 0; ti < 32; ti++) {
            const size_t row = (size_t)(b * L_ + t0 + ti);
            const float dl = delta[row * DI + d];
            const float uu = u[row * DI + d];
            const float Bv = dbc[row * 128 + 64 + lane];
            const float Cv = dbc[row * 128 + 96 + lane];
            h = fmaf(ex2f(dl * A2), h, dl * uu * Bv);
            v[ti] = h * Cv;
        }
        // butterfly multi-reduce: 31 shfl, lane l ends with y_{t0+l} in v[0]
        {
            const bool hi16 = (lane & 16) != 0;
#pragma unroll
            for (int j = 0; j < 16; j++) {
                float send = hi16 ? v[j] : v[j + 16];
                float r = __shfl_xor_sync(0xffffffffu, send, 16);
                v[j] = (hi16 ? v[j + 16] : v[j]) + r;
            }
            const bool hi8 = (lane & 8) != 0;
#pragma unroll
            for (int j = 0; j < 8; j++) {
                float send = hi8 ? v[j] : v[j + 8];
                float r = __shfl_xor_sync(0xffffffffu, send, 8);
                v[j] = (hi8 ? v[j + 8] : v[j]) + r;
            }
            const bool hi4 = (lane & 4) != 0;
#pragma unroll
            for (int j = 0; j < 4; j++) {
                float send = hi4 ? v[j] : v[j + 4];
                float r = __shfl_xor_sync(0xffffffffu, send, 4);
                v[j] = (hi4 ? v[j + 4] : v[j]) + r;
            }
            const bool hi2 = (lane & 2) != 0;
#pragma unroll
            for (int j = 0; j < 2; j++) {
                float send = hi2 ? v[j] : v[j + 2];
                float r = __shfl_xor_sync(0xffffffffu, send, 2);
                v[j] = (hi2 ? v[j + 2] : v[j]) + r;
            }
            const bool hi1 = (lane & 1) != 0;
            {
                float send = hi1 ? v[0] : v[1];
                float r = __shfl_xor_sync(0xffffffffu, send, 1);
                v[0] = (hi1 ? v[1] : v[0]) + r;
            }
        }
        __syncthreads();
        sh[lane][w] = v[0];
        __syncthreads();

        const int i  = threadIdx.x;
        const int tt = t0 + (i >> 3);
        const int dd = blockIdx.x * 8 + (i & 7);
        const size_t row = (size_t)(b * L_ + tt);
        const float yv = sh[i >> 3][i & 7];
        const float uu = u[row * DI + dd];
        const float zz = xz[row * (2 * DI) + DI + dd];
        const float yf = (yv + uu * Dp[dd]) * siluf(zz);
        half hh = __float2half(yf);
        yhi[row * DI + dd] = hh;
        ylo[row * DI + dd] = __float2half(yf - __half2float(hh));
    }
}

// ---------------- in-place LayerNorm (row = 1024) ----------------
__global__ void ln_kernel(float* __restrict__ out,
                          const float* __restrict__ gamma,
                          const float* __restrict__ beta) {
    const int row = blockIdx.x;
    float4* p = (float4*)(out + (size_t)row * DM);
    const int i = threadIdx.x;

    float4 x = p[i];
    float s = x.x + x.y + x.z + x.w;
    float q = x.x * x.x + x.y * x.y + x.z * x.z + x.w * x.w;
#pragma unroll
    for (int o = 16; o; o >>= 1) {
        s += __shfl_xor_sync(0xffffffffu, s, o);
        q += __shfl_xor_sync(0xffffffffu, q, o);
    }
    __shared__ float rs[8], rq[8];
    if ((i & 31) == 0) { rs[i >> 5] = s; rq[i >> 5] = q; }
    __syncthreads();
    s = 0.f; q = 0.f;
#pragma unroll
    for (int k = 0; k < 8; k++) { s += rs[k]; q += rq[k]; }

    const float mu  = s * (1.f / DM);
    const float var = q * (1.f / DM) - mu * mu;
    const float inv = rsqrtf(var + LN_EPS);

    const float4 gg = ((const float4*)gamma)[i];
    const float4 bb = ((const float4*)beta)[i];
    x.x = (x.x - mu) * inv * gg.x + bb.x;
    x.y = (x.y - mu) * inv * gg.y + bb.y;
    x.z = (x.z - mu) * inv * gg.z + bb.z;
    x.w = (x.w - mu) * inv * gg.w + bb.w;
    p[i] = x;
}

// ---------------- launch ----------------
extern "C" void kernel_launch(void* const* d_in, const int* in_sizes, int n_in,
                              void* d_out, int out_size) {
    (void)in_sizes; (void)n_in; (void)out_size;
    const float* x         = (const float*)d_in[0];
    const float* in_proj_w = (const float*)d_in[1];
    const float* conv_w    = (const float*)d_in[2];
    const float* conv_b    = (const float*)d_in[3];
    const float* x_proj_w  = (const float*)d_in[4];
    const float* dt_proj_w = (const float*)d_in[5];
    const float* dt_proj_b = (const float*)d_in[6];
    const float* A_log     = (const float*)d_in[7];
    const float* Dp        = (const float*)d_in[8];
    const float* out_proj_w= (const float*)d_in[9];
    const float* ln_gamma  = (const float*)d_in[10];
    const float* ln_beta   = (const float*)d_in[11];
    float* out = (float*)d_out;

    float *xz, *xc, *dbc, *delta;
    half *xhi, *xlo, *uhi, *ulo, *dthi, *dtlo, *yhi, *ylo;
    half *win, *wxp, *wdt, *wout;
    cudaGetSymbolAddress((void**)&xz,    g_xz);
    cudaGetSymbolAddress((void**)&xc,    g_xc);
    cudaGetSymbolAddress((void**)&dbc,   g_dbc);
    cudaGetSymbolAddress((void**)&delta, g_delta);
    cudaGetSymbolAddress((void**)&xhi,   g_xhi);
    cudaGetSymbolAddress((void**)&xlo,   g_xlo);
    cudaGetSymbolAddress((void**)&uhi,   g_uhi);
    cudaGetSymbolAddress((void**)&ulo,   g_ulo);
    cudaGetSymbolAddress((void**)&dthi,  g_dthi);
    cudaGetSymbolAddress((void**)&dtlo,  g_dtlo);
    cudaGetSymbolAddress((void**)&yhi,   g_yhi);
    cudaGetSymbolAddress((void**)&ylo,   g_ylo);
    cudaGetSymbolAddress((void**)&win,   g_win);
    cudaGetSymbolAddress((void**)&wxp,   g_wxp);
    cudaGetSymbolAddress((void**)&wdt,   g_wdt);
    cudaGetSymbolAddress((void**)&wout,  g_wout);

    constexpr int STG128 = 2 * APB + 128 * ROWB;   // 30720
    constexpr int STG64  = 2 * APB + 64 * ROWB;    // 25600
    constexpr int SMEM128 = 2 * STG128;            // 61440
    constexpr int SMEM64  = 2 * STG64;             // 51200
    cudaFuncSetAttribute(mma_gemm<128,0>, cudaFuncAttributeMaxDynamicSharedMemorySize, SMEM128);
    cudaFuncSetAttribute(mma_gemm<128,1>, cudaFuncAttributeMaxDynamicSharedMemorySize, SMEM128);
    cudaFuncSetAttribute(mma_gemm<64,2>,  cudaFuncAttributeMaxDynamicSharedMemorySize, SMEM64);

    // 0) weight convert+transpose ([K,N] fp32 -> [N,K] fp16)
    tconv_kernel<<<dim3(4096/32, DM/32), dim3(32,8)>>>(in_proj_w,  win,  DM, 4096);
    tconv_kernel<<<dim3(128/32,  DI/32), dim3(32,8)>>>(x_proj_w,   wxp,  DI, 128);
    tconv_kernel<<<dim3(DI/32,   DR/32), dim3(32,8)>>>(dt_proj_w,  wdt,  DR, DI);
    tconv_kernel<<<dim3(DM/32,   DI/32), dim3(32,8)>>>(out_proj_w, wout, DI, DM);
    // 0b) x split (fp16 hi/lo)
    split_kernel<<<(M_*DM/2 + 255)/256, 256>>>((const float2*)x, (uint32_t*)xhi, (uint32_t*)xlo, M_*DM/2);

    // 1) xz = x @ in_proj_w  [8192,4096]
    mma_gemm<128,0><<<dim3(4096/128, M_/128), 512, SMEM128>>>(
        xhi, xlo, win, nullptr, xz, nullptr, nullptr, DM, 4096);

    // 2) conv + silu -> xc (fp32) + uhi/ulo
    conv_silu_kernel<<<(M_*DI + 255)/256, 256>>>(xz, conv_w, conv_b, xc, uhi, ulo);

    // 3) dbc = u @ x_proj_w  [8192,128]; block x==0 also emits dt fp16 split
    mma_gemm<64,2><<<dim3(2, M_/128), 256, SMEM64>>>(
        uhi, ulo, wxp, nullptr, dbc, dthi, dtlo, DI, 128);

    // 4) delta = softplus(dt @ dt_proj_w + b)  [8192,2048]
    mma_gemm<128,1><<<dim3(DI/128, M_/128), 512, SMEM128>>>(
        dthi, dtlo, wdt, dt_proj_b, delta, nullptr, nullptr, DR, DI);

    // 5) selective scan + gating -> yhi/ylo
    scan_kernel<<<dim3(DI/8, B_), 256>>>(delta, xc, dbc, A_log, Dp, xz, yhi, ylo);

    // 6) out = y @ out_proj_w  [8192,1024]
    mma_gemm<128,0><<<dim3(DM/128, M_/128), 512, SMEM128>>>(
        yhi, ylo, wout, nullptr, out, nullptr, nullptr, DI, DM);

    // 7) in-place LayerNorm
    ln_kernel<<<M_, 256>>>(out, ln_gamma, ln_beta);
}